// round 1
// baseline (speedup 1.0000x reference)
#include <cuda_runtime.h>
#include <math.h>

// Problem constants
#define B_   32
#define L_   256
#define DM_  512
#define FF_  2048
#define E_   8
#define TK_  2
#define NPAIR (B_ * TK_)   // 64

// Scratch: post-GELU hidden activations for each (batch, slot) pair.
// 64 * 256 * 2048 floats = 128 MB (static device global: allocation-free).
__device__ float g_h[(size_t)NPAIR * L_ * FF_];
__device__ int   g_pair_e[NPAIR];
__device__ float g_pair_g[NPAIR];

__device__ __forceinline__ float gelu_exact(float x) {
    return 0.5f * x * (1.0f + erff(x * 0.70710678118654752440f));
}

// ---------------------------------------------------------------------------
// Kernel 1: gates. One thread per batch row. Matches jax _gates():
//   p = softmax(logits) * (mask==1); top-2 (stable ties); renorm by (sum+1e-9)
// ---------------------------------------------------------------------------
__global__ void gates_kernel(const float* __restrict__ logits,
                             const int*   __restrict__ masks) {
    int b = threadIdx.x;
    if (b >= B_) return;
    float p[E_];
    float mx = -1e30f;
#pragma unroll
    for (int i = 0; i < E_; i++) { p[i] = logits[b * E_ + i]; mx = fmaxf(mx, p[i]); }
    float s = 0.0f;
#pragma unroll
    for (int i = 0; i < E_; i++) { p[i] = expf(p[i] - mx); s += p[i]; }
    float inv = 1.0f / s;
#pragma unroll
    for (int i = 0; i < E_; i++) p[i] = (masks[b * E_ + i] == 1) ? p[i] * inv : 0.0f;

    // top-2 with lowest-index-first tie-break (strict >), matching lax.top_k
    int i1 = 0;
#pragma unroll
    for (int i = 1; i < E_; i++) if (p[i] > p[i1]) i1 = i;
    int i2 = -1;
#pragma unroll
    for (int i = 0; i < E_; i++) {
        if (i == i1) continue;
        if (i2 < 0 || p[i] > p[i2]) i2 = i;
    }
    float denom = p[i1] + p[i2] + 1e-9f;
    g_pair_e[2 * b + 0] = i1;  g_pair_g[2 * b + 0] = p[i1] / denom;
    g_pair_e[2 * b + 1] = i2;  g_pair_g[2 * b + 1] = p[i2] / denom;
}

// ---------------------------------------------------------------------------
// Tiled fp32 GEMM config: 128x64 block tile, BK=16, 8x4 per thread, 256 thr.
// ---------------------------------------------------------------------------
#define BM 128
#define BN 64
#define BK 16
#define TM 8
#define TN 4

// Kernel 2: h[pair] = gelu( x[b] @ W1[e] + b1[e] )
// grid: (FF_/BN=32, L_/BM=2, NPAIR=64)
__global__ void __launch_bounds__(256)
gemm1_kernel(const float* __restrict__ x,
             const float* __restrict__ W1,
             const float* __restrict__ b1) {
    const int pair = blockIdx.z;
    const int b    = pair >> 1;
    const int e    = g_pair_e[pair];

    const float* A = x  + (size_t)b * L_ * DM_;          // [256,512]
    const float* Bm = W1 + (size_t)e * DM_ * FF_;        // [512,2048]
    float*       C = g_h + (size_t)pair * L_ * FF_;      // [256,2048]

    const int m0 = blockIdx.y * BM;
    const int n0 = blockIdx.x * BN;

    __shared__ float As[BK][BM];
    __shared__ float Bs[BK][BN];

    const int tid = threadIdx.x;
    const int trow = tid >> 4;   // 0..15 (M direction)
    const int tcol = tid & 15;   // 0..15 (N direction)

    float acc[TM][TN];
#pragma unroll
    for (int i = 0; i < TM; i++)
#pragma unroll
        for (int j = 0; j < TN; j++) acc[i][j] = 0.0f;

    for (int k0 = 0; k0 < DM_; k0 += BK) {
        // load A tile 128x16 (8 elems/thread), store transposed
#pragma unroll
        for (int i = 0; i < 8; i++) {
            int idx = tid + i * 256;
            int r = idx >> 4, c = idx & 15;
            As[c][r] = A[(size_t)(m0 + r) * DM_ + k0 + c];
        }
        // load B tile 16x64 (4 elems/thread)
#pragma unroll
        for (int i = 0; i < 4; i++) {
            int idx = tid + i * 256;
            int r = idx >> 6, c = idx & 63;
            Bs[r][c] = Bm[(size_t)(k0 + r) * FF_ + n0 + c];
        }
        __syncthreads();
#pragma unroll
        for (int kk = 0; kk < BK; kk++) {
            float a[TM], bb[TN];
#pragma unroll
            for (int i = 0; i < TM; i++) a[i] = As[kk][trow * TM + i];
#pragma unroll
            for (int j = 0; j < TN; j++) bb[j] = Bs[kk][tcol * TN + j];
#pragma unroll
            for (int i = 0; i < TM; i++)
#pragma unroll
                for (int j = 0; j < TN; j++) acc[i][j] += a[i] * bb[j];
        }
        __syncthreads();
    }

    // epilogue: +bias, exact GELU
#pragma unroll
    for (int i = 0; i < TM; i++) {
        int m = m0 + trow * TM + i;
#pragma unroll
        for (int j = 0; j < TN; j++) {
            int n = n0 + tcol * TN + j;
            float v = acc[i][j] + b1[e * FF_ + n];
            C[(size_t)m * FF_ + n] = gelu_exact(v);
        }
    }
}

// Kernel 3: out[b] = sum_slot g_s * (h[b,slot] @ W2[e_s]) + sum_slot g_s*b2[e_s]
// grid: (DM_/BN=8, L_/BM=2, B_=32). Gate folded into A-tile load.
__global__ void __launch_bounds__(256)
gemm2_kernel(const float* __restrict__ W2,
             const float* __restrict__ b2,
             float*       __restrict__ out) {
    const int b  = blockIdx.z;
    const int m0 = blockIdx.y * BM;
    const int n0 = blockIdx.x * BN;

    __shared__ float As[BK][BM];
    __shared__ float Bs[BK][BN];

    const int tid = threadIdx.x;
    const int trow = tid >> 4;
    const int tcol = tid & 15;

    float acc[TM][TN];
#pragma unroll
    for (int i = 0; i < TM; i++)
#pragma unroll
        for (int j = 0; j < TN; j++) acc[i][j] = 0.0f;

    for (int slot = 0; slot < TK_; slot++) {
        const int   pair = 2 * b + slot;
        const int   e    = g_pair_e[pair];
        const float g    = g_pair_g[pair];
        const float* A  = g_h + (size_t)pair * L_ * FF_;   // [256,2048] post-GELU
        const float* Bm = W2 + (size_t)e * FF_ * DM_;      // [2048,512]

        for (int k0 = 0; k0 < FF_; k0 += BK) {
#pragma unroll
            for (int i = 0; i < 8; i++) {
                int idx = tid + i * 256;
                int r = idx >> 4, c = idx & 15;
                As[c][r] = g * A[(size_t)(m0 + r) * FF_ + k0 + c];
            }
#pragma unroll
            for (int i = 0; i < 4; i++) {
                int idx = tid + i * 256;
                int r = idx >> 6, c = idx & 63;
                Bs[r][c] = Bm[(size_t)(k0 + r) * DM_ + n0 + c];
            }
            __syncthreads();
#pragma unroll
            for (int kk = 0; kk < BK; kk++) {
                float a[TM], bb[TN];
#pragma unroll
                for (int i = 0; i < TM; i++) a[i] = As[kk][trow * TM + i];
#pragma unroll
                for (int j = 0; j < TN; j++) bb[j] = Bs[kk][tcol * TN + j];
#pragma unroll
                for (int i = 0; i < TM; i++)
#pragma unroll
                    for (int j = 0; j < TN; j++) acc[i][j] += a[i] * bb[j];
            }
            __syncthreads();
        }
    }

    // epilogue: gated bias combine, write output
    const int   e0 = g_pair_e[2 * b + 0], e1 = g_pair_e[2 * b + 1];
    const float g0 = g_pair_g[2 * b + 0], g1 = g_pair_g[2 * b + 1];

#pragma unroll
    for (int i = 0; i < TM; i++) {
        int m = m0 + trow * TM + i;
#pragma unroll
        for (int j = 0; j < TN; j++) {
            int n = n0 + tcol * TN + j;
            float bias = g0 * b2[e0 * DM_ + n] + g1 * b2[e1 * DM_ + n];
            out[((size_t)b * L_ + m) * DM_ + n] = acc[i][j] + bias;
        }
    }
}

// ---------------------------------------------------------------------------
// Launch
// ---------------------------------------------------------------------------
extern "C" void kernel_launch(void* const* d_in, const int* in_sizes, int n_in,
                              void* d_out, int out_size) {
    const float* x      = (const float*)d_in[0];  // [32,256,512]
    const float* logits = (const float*)d_in[1];  // [32,8]
    const int*   masks  = (const int*)  d_in[2];  // [32,8]
    const float* W1     = (const float*)d_in[3];  // [8,512,2048]
    const float* b1     = (const float*)d_in[4];  // [8,2048]
    const float* W2     = (const float*)d_in[5];  // [8,2048,512]
    const float* b2     = (const float*)d_in[6];  // [8,512]
    float* out = (float*)d_out;                   // [32,256,512]

    gates_kernel<<<1, 32>>>(logits, masks);

    dim3 grid1(FF_ / BN, L_ / BM, NPAIR);   // (32, 2, 64)
    gemm1_kernel<<<grid1, 256>>>(x, W1, b1);

    dim3 grid2(DM_ / BN, L_ / BM, B_);      // (8, 2, 32)
    gemm2_kernel<<<grid2, 256>>>(W2, b2, out);
}

// round 5
// speedup vs baseline: 3.7695x; 3.7695x over previous
#include <cuda_runtime.h>
#include <cuda_bf16.h>
#include <math.h>
#include <stdint.h>

#define B_   32
#define L_   256
#define DM_  512
#define FF_  2048
#define E_   8
#define NPAIR 64

// ---------------- device scratch (static = allocation-free) ----------------
__device__ int   g_pair_e[NPAIR];
__device__ float g_pair_g[NPAIR];
// x split:  [B*L][2*DM]   row = [hi(0..511) | lo(0..511)]
__device__ __align__(256) __nv_bfloat16 g_x2[(size_t)B_ * L_ * 2 * DM_];
// W1^T split: [E][FF][2*DM]
__device__ __align__(256) __nv_bfloat16 g_w1t[(size_t)E_ * FF_ * 2 * DM_];
// W2^T split: [E][DM][2*FF]
__device__ __align__(256) __nv_bfloat16 g_w2t[(size_t)E_ * DM_ * 2 * FF_];
// g*gelu(h) split: [pair][L][2*FF]
__device__ __align__(256) __nv_bfloat16 g_gh[(size_t)NPAIR * L_ * 2 * FF_];

// ---------------- helpers ----------------
__device__ __forceinline__ uint32_t smem_u32(const void* p) {
    uint32_t a;
    asm("{ .reg .u64 t; cvta.to.shared.u64 t, %1; cvt.u32.u64 %0, t; }" : "=r"(a) : "l"(p));
    return a;
}
__device__ __forceinline__ void cp16(uint32_t dst, const void* src) {
    asm volatile("cp.async.cg.shared.global [%0], [%1], 16;" :: "r"(dst), "l"(src));
}
#define CP_COMMIT() asm volatile("cp.async.commit_group;" ::: "memory")

__device__ __forceinline__ void ldsm_x4(uint32_t& r0, uint32_t& r1, uint32_t& r2, uint32_t& r3, uint32_t a) {
    asm volatile("ldmatrix.sync.aligned.m8n8.x4.shared.b16 {%0,%1,%2,%3}, [%4];"
                 : "=r"(r0), "=r"(r1), "=r"(r2), "=r"(r3) : "r"(a));
}
__device__ __forceinline__ void ldsm_x2(uint32_t& r0, uint32_t& r1, uint32_t a) {
    asm volatile("ldmatrix.sync.aligned.m8n8.x2.shared.b16 {%0,%1}, [%2];"
                 : "=r"(r0), "=r"(r1) : "r"(a));
}
__device__ __forceinline__ void mma_bf16(float* c, uint32_t a0, uint32_t a1, uint32_t a2, uint32_t a3,
                                         uint32_t b0, uint32_t b1) {
    asm volatile("mma.sync.aligned.m16n8k16.row.col.f32.bf16.bf16.f32 "
                 "{%0,%1,%2,%3}, {%4,%5,%6,%7}, {%8,%9}, {%0,%1,%2,%3};"
                 : "+f"(c[0]), "+f"(c[1]), "+f"(c[2]), "+f"(c[3])
                 : "r"(a0), "r"(a1), "r"(a2), "r"(a3), "r"(b0), "r"(b1));
}
__device__ __forceinline__ float gelu_exact(float x) {
    return 0.5f * x * (1.0f + erff(x * 0.70710678118654752440f));
}

// Load a ROWS x 64 bf16 tile (128B rows, XOR swizzle chunk^=(row&7)) via cp.async.
template<int ROWS>
__device__ __forceinline__ void load_tile(uint32_t dst, const __nv_bfloat16* src, int ld, int tid) {
    constexpr int ITER = ROWS * 8 / 256;
#pragma unroll
    for (int j = 0; j < ITER; j++) {
        int idx = tid + j * 256;
        int r = idx >> 3, c = idx & 7;
        uint32_t off = (uint32_t)(r * 128 + ((c ^ (r & 7)) * 16));
        cp16(dst + off, (const char*)src + (size_t)r * ld * 2 + c * 16);
    }
}

// One 64-wide K chunk. A tile at aBase (128x64), B tile at bBase (64x64).
// Warp tile 32x32: MF=2, NF=4.
__device__ __forceinline__ void compute_chunk(float (&acc)[2][4][4],
                                              uint32_t aBase, uint32_t bBase,
                                              int wm, int wn, int lane) {
#pragma unroll
    for (int ks = 0; ks < 4; ks++) {
        uint32_t afr[2][4];
#pragma unroll
        for (int mf = 0; mf < 2; mf++) {
            int r = wm + mf * 16 + (lane & 15);
            int c = ks * 2 + (lane >> 4);
            uint32_t addr = aBase + (uint32_t)(r * 128 + ((c ^ (r & 7)) * 16));
            ldsm_x4(afr[mf][0], afr[mf][1], afr[mf][2], afr[mf][3], addr);
        }
#pragma unroll
        for (int nf = 0; nf < 4; nf++) {
            int r = wn + nf * 8 + (lane & 7);
            int c = ks * 2 + ((lane >> 3) & 1);
            uint32_t addr = bBase + (uint32_t)(r * 128 + ((c ^ (r & 7)) * 16));
            uint32_t b0, b1;
            ldsm_x2(b0, b1, addr);
#pragma unroll
            for (int mf = 0; mf < 2; mf++)
                mma_bf16(acc[mf][nf], afr[mf][0], afr[mf][1], afr[mf][2], afr[mf][3], b0, b1);
        }
    }
}

// ---------------------------------------------------------------------------
// gates
// ---------------------------------------------------------------------------
__global__ void gates_kernel(const float* __restrict__ logits, const int* __restrict__ masks) {
    int b = threadIdx.x;
    if (b >= B_) return;
    float p[E_];
    float mx = -1e30f;
#pragma unroll
    for (int i = 0; i < E_; i++) { p[i] = logits[b * E_ + i]; mx = fmaxf(mx, p[i]); }
    float s = 0.0f;
#pragma unroll
    for (int i = 0; i < E_; i++) { p[i] = expf(p[i] - mx); s += p[i]; }
    float inv = 1.0f / s;
#pragma unroll
    for (int i = 0; i < E_; i++) p[i] = (masks[b * E_ + i] == 1) ? p[i] * inv : 0.0f;
    int i1 = 0;
#pragma unroll
    for (int i = 1; i < E_; i++) if (p[i] > p[i1]) i1 = i;
    int i2 = -1;
#pragma unroll
    for (int i = 0; i < E_; i++) {
        if (i == i1) continue;
        if (i2 < 0 || p[i] > p[i2]) i2 = i;
    }
    float denom = p[i1] + p[i2] + 1e-9f;
    g_pair_e[2 * b + 0] = i1;  g_pair_g[2 * b + 0] = p[i1] / denom;
    g_pair_e[2 * b + 1] = i2;  g_pair_g[2 * b + 1] = p[i2] / denom;
}

// ---------------------------------------------------------------------------
// prep: split x into [hi|lo] rows of 1024 (writes g_x2 from DEVICE code)
// ---------------------------------------------------------------------------
__global__ void cvt_split_kernel(const float* __restrict__ X) {
    size_t i = (size_t)blockIdx.x * blockDim.x + threadIdx.x;
    if (i >= (size_t)B_ * L_ * DM_) return;
    size_t row = i / DM_;
    int k = (int)(i % DM_);
    float v = X[i];
    __nv_bfloat16 h = __float2bfloat16(v);
    g_x2[row * (2 * DM_) + k] = h;
    g_x2[row * (2 * DM_) + DM_ + k] = __float2bfloat16(v - __bfloat162float(h));
}

// prep: transpose W [E][K][N] -> T [E][N][2K] ([hi|lo] rows).
// NOTE: destination is the __device__ symbol referenced from DEVICE code —
// never passed as a host-side kernel argument (host shadow address + GB300 ATS
// silently swallowed the writes in rounds 3/4).
template<int K, int N>
__device__ __forceinline__ void transpose_cvt_body(const float* __restrict__ W,
                                                   __nv_bfloat16* __restrict__ T) {
    __shared__ float s[32][33];
    int e = blockIdx.z;
    int n0 = blockIdx.x * 32, k0 = blockIdx.y * 32;
    const float* Wp = W + (size_t)e * K * N;
#pragma unroll
    for (int i = 0; i < 32; i += 8)
        s[threadIdx.y + i][threadIdx.x] = Wp[(size_t)(k0 + threadIdx.y + i) * N + n0 + threadIdx.x];
    __syncthreads();
#pragma unroll
    for (int i = 0; i < 32; i += 8) {
        int n = n0 + threadIdx.y + i;
        int k = k0 + threadIdx.x;
        float v = s[threadIdx.x][threadIdx.y + i];
        __nv_bfloat16 h = __float2bfloat16(v);
        __nv_bfloat16* rowp = T + ((size_t)e * N + n) * (2 * (size_t)K);
        rowp[k]     = h;
        rowp[K + k] = __float2bfloat16(v - __bfloat162float(h));
    }
}
__global__ void transpose_cvt_w1(const float* __restrict__ W) {
    transpose_cvt_body<DM_, FF_>(W, g_w1t);
}
__global__ void transpose_cvt_w2(const float* __restrict__ W) {
    transpose_cvt_body<FF_, DM_>(W, g_w2t);
}

// ---------------------------------------------------------------------------
// GEMM1: gh[pair] = g * gelu(x[b] @ W1[e] + b1[e]) -> bf16 hi/lo rows of 4096
// BM=128, BN=64, K-chunk=64, 2-stage pipeline (48KB smem, no opt-in needed)
// virtual K = 3*512 (phases hh, lh, hl); grid (FF/64=32, L/128=2, 64)
// ---------------------------------------------------------------------------
#define G_STAGE 24576u   // A 16KB + B 8KB
#define G_SMEM  49152    // 2 stages == 48KB default limit, no attribute needed

__global__ void __launch_bounds__(256, 1)
gemm1_mma(const float* __restrict__ b1p) {
    extern __shared__ __align__(128) char smem[];
    const int tid = threadIdx.x, lane = tid & 31, wid = tid >> 5;
    const int pair = blockIdx.z;
    const int e = g_pair_e[pair];
    const float g = g_pair_g[pair];
    const int m0 = blockIdx.y * 128, n0 = blockIdx.x * 64;

    const __nv_bfloat16* Abase = g_x2  + ((size_t)(pair >> 1) * L_ + m0) * (2 * DM_);
    const __nv_bfloat16* Bbase = g_w1t + ((size_t)e * FF_ + n0) * (2 * DM_);

    uint32_t s0 = smem_u32(smem);
    const int wm = (wid >> 1) * 32, wn = (wid & 1) * 32;

    float acc[2][4][4] = {};
    const int NC = 24;   // 3 phases * 8 chunks

#define G1_OFF(c, ka, kb) do { int _ph = (c) >> 3; int _kk = ((c) & 7) * 64; \
        ka = _kk + (_ph == 1 ? DM_ : 0); kb = _kk + (_ph == 2 ? DM_ : 0); } while (0)

#pragma unroll
    for (int sc = 0; sc < 2; sc++) {
        int ka, kb; G1_OFF(sc, ka, kb);
        load_tile<128>(s0 + sc * G_STAGE,          Abase + ka, 2 * DM_, tid);
        load_tile<64> (s0 + sc * G_STAGE + 16384u, Bbase + kb, 2 * DM_, tid);
        CP_COMMIT();
    }
    for (int c = 0; c < NC; c++) {
        if (c == NC - 1) asm volatile("cp.async.wait_group 0;" ::: "memory");
        else             asm volatile("cp.async.wait_group 1;" ::: "memory");
        __syncthreads();
        uint32_t sbuf = s0 + (uint32_t)(c & 1) * G_STAGE;
        compute_chunk(acc, sbuf, sbuf + 16384u, wm, wn, lane);
        __syncthreads();
        int nc = c + 2;
        if (nc < NC) {
            int ka, kb; G1_OFF(nc, ka, kb);
            uint32_t dbuf = s0 + (uint32_t)(nc & 1) * G_STAGE;
            load_tile<128>(dbuf,          Abase + ka, 2 * DM_, tid);
            load_tile<64> (dbuf + 16384u, Bbase + kb, 2 * DM_, tid);
            CP_COMMIT();
        }
    }
#undef G1_OFF

    // epilogue: +bias, gelu, *gate, split hi/lo, store
    const float* b1e = b1p + (size_t)e * FF_;
#pragma unroll
    for (int mf = 0; mf < 2; mf++) {
#pragma unroll
        for (int h = 0; h < 2; h++) {
            int r = m0 + wm + mf * 16 + (lane >> 2) + 8 * h;
            __nv_bfloat16* rowp = g_gh + ((size_t)pair * L_ + r) * (2 * FF_);
#pragma unroll
            for (int nf = 0; nf < 4; nf++) {
                int n = n0 + wn + nf * 8 + (lane & 3) * 2;
                float v0 = acc[mf][nf][2 * h + 0] + __ldg(b1e + n);
                float v1 = acc[mf][nf][2 * h + 1] + __ldg(b1e + n + 1);
                v0 = gelu_exact(v0) * g;
                v1 = gelu_exact(v1) * g;
                __nv_bfloat16 h0 = __float2bfloat16(v0), h1 = __float2bfloat16(v1);
                __nv_bfloat162 hv; hv.x = h0; hv.y = h1;
                __nv_bfloat162 lv;
                lv.x = __float2bfloat16(v0 - __bfloat162float(h0));
                lv.y = __float2bfloat16(v1 - __bfloat162float(h1));
                *(__nv_bfloat162*)(rowp + n)       = hv;
                *(__nv_bfloat162*)(rowp + FF_ + n) = lv;
            }
        }
    }
}

// ---------------------------------------------------------------------------
// GEMM2: out[b] = sum_slot (g*h)[b,slot] @ W2[e_slot] + gated bias
// BM=128, BN=64, 2-stage, virtual K = 2 slots * 3*2048; grid (DM/64=8, 2, 32)
// ---------------------------------------------------------------------------
__global__ void __launch_bounds__(256, 1)
gemm2_mma(const float* __restrict__ b2p, float* __restrict__ out) {
    extern __shared__ __align__(128) char smem[];
    const int tid = threadIdx.x, lane = tid & 31, wid = tid >> 5;
    const int bb = blockIdx.z;
    const int m0 = blockIdx.y * 128, n0 = blockIdx.x * 64;
    const int e0 = g_pair_e[2 * bb + 0], e1 = g_pair_e[2 * bb + 1];
    const float g0 = g_pair_g[2 * bb + 0], g1 = g_pair_g[2 * bb + 1];

    const __nv_bfloat16* Ab[2] = {
        g_gh + ((size_t)(2 * bb + 0) * L_ + m0) * (2 * FF_),
        g_gh + ((size_t)(2 * bb + 1) * L_ + m0) * (2 * FF_)
    };
    const __nv_bfloat16* Bb[2] = {
        g_w2t + ((size_t)e0 * DM_ + n0) * (2 * FF_),
        g_w2t + ((size_t)e1 * DM_ + n0) * (2 * FF_)
    };

    uint32_t s0 = smem_u32(smem);
    const int wm = (wid >> 1) * 32, wn = (wid & 1) * 32;

    float acc[2][4][4] = {};
    const int NC = 192;   // 2 slots * 3 phases * 32 chunks

#define G2_SRC(c, pa, pb) do { \
        int _sl = ((c) >= 96) ? 1 : 0; int _cc = (c) - _sl * 96; \
        int _ph = _cc >> 5; int _kk = (_cc & 31) << 6; \
        pa = Ab[_sl] + _kk + (_ph == 1 ? FF_ : 0); \
        pb = Bb[_sl] + _kk + (_ph == 2 ? FF_ : 0); } while (0)

#pragma unroll
    for (int sc = 0; sc < 2; sc++) {
        const __nv_bfloat16 *pa, *pb; G2_SRC(sc, pa, pb);
        load_tile<128>(s0 + sc * G_STAGE,          pa, 2 * FF_, tid);
        load_tile<64> (s0 + sc * G_STAGE + 16384u, pb, 2 * FF_, tid);
        CP_COMMIT();
    }
    for (int c = 0; c < NC; c++) {
        if (c == NC - 1) asm volatile("cp.async.wait_group 0;" ::: "memory");
        else             asm volatile("cp.async.wait_group 1;" ::: "memory");
        __syncthreads();
        uint32_t sbuf = s0 + (uint32_t)(c & 1) * G_STAGE;
        compute_chunk(acc, sbuf, sbuf + 16384u, wm, wn, lane);
        __syncthreads();
        int nc = c + 2;
        if (nc < NC) {
            const __nv_bfloat16 *pa, *pb; G2_SRC(nc, pa, pb);
            uint32_t dbuf = s0 + (uint32_t)(nc & 1) * G_STAGE;
            load_tile<128>(dbuf,          pa, 2 * FF_, tid);
            load_tile<64> (dbuf + 16384u, pb, 2 * FF_, tid);
            CP_COMMIT();
        }
    }
#undef G2_SRC

    const float* b2e0 = b2p + (size_t)e0 * DM_;
    const float* b2e1 = b2p + (size_t)e1 * DM_;
#pragma unroll
    for (int mf = 0; mf < 2; mf++) {
#pragma unroll
        for (int h = 0; h < 2; h++) {
            int r = m0 + wm + mf * 16 + (lane >> 2) + 8 * h;
            float* op = out + ((size_t)bb * L_ + r) * DM_;
#pragma unroll
            for (int nf = 0; nf < 4; nf++) {
                int n = n0 + wn + nf * 8 + (lane & 3) * 2;
                float2 v;
                v.x = acc[mf][nf][2 * h + 0] + g0 * __ldg(b2e0 + n)     + g1 * __ldg(b2e1 + n);
                v.y = acc[mf][nf][2 * h + 1] + g0 * __ldg(b2e0 + n + 1) + g1 * __ldg(b2e1 + n + 1);
                *(float2*)(op + n) = v;
            }
        }
    }
}

// ---------------------------------------------------------------------------
// launch — kernel launches only; no host-side state, no attribute calls,
// no __device__ symbols passed as host arguments.
// ---------------------------------------------------------------------------
extern "C" void kernel_launch(void* const* d_in, const int* in_sizes, int n_in,
                              void* d_out, int out_size) {
    const float* x      = (const float*)d_in[0];
    const float* logits = (const float*)d_in[1];
    const int*   masks  = (const int*)  d_in[2];
    const float* W1     = (const float*)d_in[3];
    const float* b1     = (const float*)d_in[4];
    const float* W2     = (const float*)d_in[5];
    const float* b2     = (const float*)d_in[6];
    float* out = (float*)d_out;

    gates_kernel<<<1, 32>>>(logits, masks);

    size_t nx = (size_t)B_ * L_ * DM_;
    cvt_split_kernel<<<(unsigned)((nx + 255) / 256), 256>>>(x);

    dim3 tb(32, 8);
    transpose_cvt_w1<<<dim3(FF_ / 32, DM_ / 32, E_), tb>>>(W1);
    transpose_cvt_w2<<<dim3(DM_ / 32, FF_ / 32, E_), tb>>>(W2);

    gemm1_mma<<<dim3(FF_ / 64, L_ / 128, NPAIR), 256, G_SMEM>>>(b1);
    gemm2_mma<<<dim3(DM_ / 64, L_ / 128, B_), 256, G_SMEM>>>(b2, out);
}

// round 6
// speedup vs baseline: 4.1834x; 1.1098x over previous
#include <cuda_runtime.h>
#include <cuda_bf16.h>
#include <math.h>
#include <stdint.h>

#define B_   32
#define L_   256
#define DM_  512
#define FF_  2048
#define E_   8
#define NPAIR 64

// ---------------- device scratch (static = allocation-free) ----------------
__device__ int   g_pair_e[NPAIR];
__device__ float g_pair_g[NPAIR];
// x split:  [B*L][2*DM]   row = [hi(0..511) | lo(0..511)]
__device__ __align__(256) __nv_bfloat16 g_x2[(size_t)B_ * L_ * 2 * DM_];
// W1^T split: [E][FF][2*DM]
__device__ __align__(256) __nv_bfloat16 g_w1t[(size_t)E_ * FF_ * 2 * DM_];
// W2^T split: [E][DM][2*FF]
__device__ __align__(256) __nv_bfloat16 g_w2t[(size_t)E_ * DM_ * 2 * FF_];
// g*gelu(h) split: [pair][L][2*FF]
__device__ __align__(256) __nv_bfloat16 g_gh[(size_t)NPAIR * L_ * 2 * FF_];

// ---------------- helpers ----------------
__device__ __forceinline__ uint32_t smem_u32(const void* p) {
    uint32_t a;
    asm("{ .reg .u64 t; cvta.to.shared.u64 t, %1; cvt.u32.u64 %0, t; }" : "=r"(a) : "l"(p));
    return a;
}
__device__ __forceinline__ void cp16(uint32_t dst, const void* src) {
    asm volatile("cp.async.cg.shared.global [%0], [%1], 16;" :: "r"(dst), "l"(src));
}
#define CP_COMMIT() asm volatile("cp.async.commit_group;" ::: "memory")

__device__ __forceinline__ void ldsm_x4(uint32_t& r0, uint32_t& r1, uint32_t& r2, uint32_t& r3, uint32_t a) {
    asm volatile("ldmatrix.sync.aligned.m8n8.x4.shared.b16 {%0,%1,%2,%3}, [%4];"
                 : "=r"(r0), "=r"(r1), "=r"(r2), "=r"(r3) : "r"(a));
}
__device__ __forceinline__ void ldsm_x2(uint32_t& r0, uint32_t& r1, uint32_t a) {
    asm volatile("ldmatrix.sync.aligned.m8n8.x2.shared.b16 {%0,%1}, [%2];"
                 : "=r"(r0), "=r"(r1) : "r"(a));
}
__device__ __forceinline__ void mma_bf16(float* c, uint32_t a0, uint32_t a1, uint32_t a2, uint32_t a3,
                                         uint32_t b0, uint32_t b1) {
    asm volatile("mma.sync.aligned.m16n8k16.row.col.f32.bf16.bf16.f32 "
                 "{%0,%1,%2,%3}, {%4,%5,%6,%7}, {%8,%9}, {%0,%1,%2,%3};"
                 : "+f"(c[0]), "+f"(c[1]), "+f"(c[2]), "+f"(c[3])
                 : "r"(a0), "r"(a1), "r"(a2), "r"(a3), "r"(b0), "r"(b1));
}
__device__ __forceinline__ float gelu_exact(float x) {
    return 0.5f * x * (1.0f + erff(x * 0.70710678118654752440f));
}

// Load a ROWS x 64 bf16 tile (128B rows, XOR swizzle chunk^=(row&7)) via cp.async.
template<int ROWS>
__device__ __forceinline__ void load_tile(uint32_t dst, const __nv_bfloat16* src, int ld, int tid) {
    constexpr int ITER = ROWS * 8 / 256;
#pragma unroll
    for (int j = 0; j < ITER; j++) {
        int idx = tid + j * 256;
        int r = idx >> 3, c = idx & 7;
        uint32_t off = (uint32_t)(r * 128 + ((c ^ (r & 7)) * 16));
        cp16(dst + off, (const char*)src + (size_t)r * ld * 2 + c * 16);
    }
}

// One 64-wide K pass over warp tile (MF*16) x (NF*8).
template<int MF, int NF>
__device__ __forceinline__ void compute_pass(float (&acc)[MF][NF][4],
                                             uint32_t aBase, uint32_t bBase,
                                             int wm, int wn, int lane) {
#pragma unroll
    for (int ks = 0; ks < 4; ks++) {
        uint32_t afr[MF][4];
#pragma unroll
        for (int mf = 0; mf < MF; mf++) {
            int r = wm + mf * 16 + (lane & 15);
            int c = ks * 2 + (lane >> 4);
            uint32_t addr = aBase + (uint32_t)(r * 128 + ((c ^ (r & 7)) * 16));
            ldsm_x4(afr[mf][0], afr[mf][1], afr[mf][2], afr[mf][3], addr);
        }
#pragma unroll
        for (int nf = 0; nf < NF; nf++) {
            int r = wn + nf * 8 + (lane & 7);
            int c = ks * 2 + ((lane >> 3) & 1);
            uint32_t addr = bBase + (uint32_t)(r * 128 + ((c ^ (r & 7)) * 16));
            uint32_t b0, b1;
            ldsm_x2(b0, b1, addr);
#pragma unroll
            for (int mf = 0; mf < MF; mf++)
                mma_bf16(acc[mf][nf], afr[mf][0], afr[mf][1], afr[mf][2], afr[mf][3], b0, b1);
        }
    }
}

// ---------------------------------------------------------------------------
// gates
// ---------------------------------------------------------------------------
__global__ void gates_kernel(const float* __restrict__ logits, const int* __restrict__ masks) {
    int b = threadIdx.x;
    if (b >= B_) return;
    float p[E_];
    float mx = -1e30f;
#pragma unroll
    for (int i = 0; i < E_; i++) { p[i] = logits[b * E_ + i]; mx = fmaxf(mx, p[i]); }
    float s = 0.0f;
#pragma unroll
    for (int i = 0; i < E_; i++) { p[i] = expf(p[i] - mx); s += p[i]; }
    float inv = 1.0f / s;
#pragma unroll
    for (int i = 0; i < E_; i++) p[i] = (masks[b * E_ + i] == 1) ? p[i] * inv : 0.0f;
    int i1 = 0;
#pragma unroll
    for (int i = 1; i < E_; i++) if (p[i] > p[i1]) i1 = i;
    int i2 = -1;
#pragma unroll
    for (int i = 0; i < E_; i++) {
        if (i == i1) continue;
        if (i2 < 0 || p[i] > p[i2]) i2 = i;
    }
    float denom = p[i1] + p[i2] + 1e-9f;
    g_pair_e[2 * b + 0] = i1;  g_pair_g[2 * b + 0] = p[i1] / denom;
    g_pair_e[2 * b + 1] = i2;  g_pair_g[2 * b + 1] = p[i2] / denom;
}

// ---------------------------------------------------------------------------
// prep: split x into [hi|lo] rows of 1024 (device-symbol writes from device code)
// ---------------------------------------------------------------------------
__global__ void cvt_split_kernel(const float* __restrict__ X) {
    size_t i = (size_t)blockIdx.x * blockDim.x + threadIdx.x;
    if (i >= (size_t)B_ * L_ * DM_) return;
    size_t row = i / DM_;
    int k = (int)(i % DM_);
    float v = X[i];
    __nv_bfloat16 h = __float2bfloat16(v);
    g_x2[row * (2 * DM_) + k] = h;
    g_x2[row * (2 * DM_) + DM_ + k] = __float2bfloat16(v - __bfloat162float(h));
}

// prep: transpose W [E][K][N] -> T [E][N][2K] ([hi|lo] rows)
template<int K, int N>
__device__ __forceinline__ void transpose_cvt_body(const float* __restrict__ W,
                                                   __nv_bfloat16* __restrict__ T) {
    __shared__ float s[32][33];
    int e = blockIdx.z;
    int n0 = blockIdx.x * 32, k0 = blockIdx.y * 32;
    const float* Wp = W + (size_t)e * K * N;
#pragma unroll
    for (int i = 0; i < 32; i += 8)
        s[threadIdx.y + i][threadIdx.x] = Wp[(size_t)(k0 + threadIdx.y + i) * N + n0 + threadIdx.x];
    __syncthreads();
#pragma unroll
    for (int i = 0; i < 32; i += 8) {
        int n = n0 + threadIdx.y + i;
        int k = k0 + threadIdx.x;
        float v = s[threadIdx.x][threadIdx.y + i];
        __nv_bfloat16 h = __float2bfloat16(v);
        __nv_bfloat16* rowp = T + ((size_t)e * N + n) * (2 * (size_t)K);
        rowp[k]     = h;
        rowp[K + k] = __float2bfloat16(v - __bfloat162float(h));
    }
}
__global__ void transpose_cvt_w1(const float* __restrict__ W) {
    transpose_cvt_body<DM_, FF_>(W, g_w1t);
}
__global__ void transpose_cvt_w2(const float* __restrict__ W) {
    transpose_cvt_body<FF_, DM_>(W, g_w2t);
}

// ---------------------------------------------------------------------------
// GEMM1: gh[pair] = g * gelu(x[b] @ W1[e] + b1[e]) -> bf16 hi/lo rows of 4096
// BM=128, BN=256, kc=64; stage = Ah16+Al16+Bh32+Bl32 = 96KB; 2 stages (192KB)
// 3 passes per chunk from SMEM: AhBh, AlBh, AhBl. Grid (8, 2, 64) = 1024 CTAs.
// ---------------------------------------------------------------------------
#define G1_STAGE  98304u
#define G1_A_L    16384u
#define G1_B_H    32768u
#define G1_B_L    65536u
#define G1_SMEM   (2 * 98304)

__global__ void __launch_bounds__(256, 1)
gemm1_mma(const float* __restrict__ b1p) {
    extern __shared__ __align__(128) char smem[];
    const int tid = threadIdx.x, lane = tid & 31, wid = tid >> 5;
    const int pair = blockIdx.z;
    const int e = g_pair_e[pair];
    const float g = g_pair_g[pair];
    const int m0 = blockIdx.y * 128, n0 = blockIdx.x * 256;

    const __nv_bfloat16* Abase = g_x2  + ((size_t)(pair >> 1) * L_ + m0) * (2 * DM_);
    const __nv_bfloat16* Bbase = g_w1t + ((size_t)e * FF_ + n0) * (2 * DM_);

    uint32_t s0 = smem_u32(smem);
    const int wm = (wid >> 2) * 64, wn = (wid & 3) * 64;   // warp tile 64x64

    float acc[4][8][4] = {};
    const int NC = 8;   // 512 / 64

#define G1_LOAD(c, buf) do { int _k = (c) * 64; uint32_t _d = s0 + (buf) * G1_STAGE; \
        load_tile<128>(_d,          Abase + _k,       2 * DM_, tid); \
        load_tile<128>(_d + G1_A_L, Abase + DM_ + _k, 2 * DM_, tid); \
        load_tile<256>(_d + G1_B_H, Bbase + _k,       2 * DM_, tid); \
        load_tile<256>(_d + G1_B_L, Bbase + DM_ + _k, 2 * DM_, tid); \
        CP_COMMIT(); } while (0)

    G1_LOAD(0, 0);
    G1_LOAD(1, 1);
    for (int c = 0; c < NC; c++) {
        if (c == NC - 1) asm volatile("cp.async.wait_group 0;" ::: "memory");
        else             asm volatile("cp.async.wait_group 1;" ::: "memory");
        __syncthreads();
        uint32_t sb = s0 + (uint32_t)(c & 1) * G1_STAGE;
        compute_pass<4, 8>(acc, sb,          sb + G1_B_H, wm, wn, lane);  // Ah*Bh
        compute_pass<4, 8>(acc, sb + G1_A_L, sb + G1_B_H, wm, wn, lane);  // Al*Bh
        compute_pass<4, 8>(acc, sb,          sb + G1_B_L, wm, wn, lane);  // Ah*Bl
        __syncthreads();
        if (c + 2 < NC) G1_LOAD(c + 2, (c + 2) & 1);
    }
#undef G1_LOAD

    // epilogue: +bias, gelu, *gate, split hi/lo, store
    const float* b1e = b1p + (size_t)e * FF_;
#pragma unroll
    for (int mf = 0; mf < 4; mf++) {
#pragma unroll
        for (int h = 0; h < 2; h++) {
            int r = m0 + wm + mf * 16 + (lane >> 2) + 8 * h;
            __nv_bfloat16* rowp = g_gh + ((size_t)pair * L_ + r) * (2 * FF_);
#pragma unroll
            for (int nf = 0; nf < 8; nf++) {
                int n = n0 + wn + nf * 8 + (lane & 3) * 2;
                float v0 = acc[mf][nf][2 * h + 0] + __ldg(b1e + n);
                float v1 = acc[mf][nf][2 * h + 1] + __ldg(b1e + n + 1);
                v0 = gelu_exact(v0) * g;
                v1 = gelu_exact(v1) * g;
                __nv_bfloat16 h0 = __float2bfloat16(v0), h1 = __float2bfloat16(v1);
                __nv_bfloat162 hv; hv.x = h0; hv.y = h1;
                __nv_bfloat162 lv;
                lv.x = __float2bfloat16(v0 - __bfloat162float(h0));
                lv.y = __float2bfloat16(v1 - __bfloat162float(h1));
                *(__nv_bfloat162*)(rowp + n)       = hv;
                *(__nv_bfloat162*)(rowp + FF_ + n) = lv;
            }
        }
    }
}

// ---------------------------------------------------------------------------
// GEMM2: out[b] = sum_slot (g*h)[b,slot] @ W2[e_slot] + gated bias
// BM=128, BN=128, kc=64; stage = Ah16+Al16+Bh16+Bl16 = 64KB; 2 stages (128KB)
// virtual K = 2 slots * 2048; grid (4, 2, 32) = 256 CTAs.
// ---------------------------------------------------------------------------
#define G2_STAGE  65536u
#define G2_A_L    16384u
#define G2_B_H    32768u
#define G2_B_L    49152u
#define G2_SMEM   (2 * 65536)

__global__ void __launch_bounds__(256, 1)
gemm2_mma(const float* __restrict__ b2p, float* __restrict__ out) {
    extern __shared__ __align__(128) char smem[];
    const int tid = threadIdx.x, lane = tid & 31, wid = tid >> 5;
    const int bb = blockIdx.z;
    const int m0 = blockIdx.y * 128, n0 = blockIdx.x * 128;
    const int e0 = g_pair_e[2 * bb + 0], e1 = g_pair_e[2 * bb + 1];
    const float g0 = g_pair_g[2 * bb + 0], g1 = g_pair_g[2 * bb + 1];

    const __nv_bfloat16* Ab[2] = {
        g_gh + ((size_t)(2 * bb + 0) * L_ + m0) * (2 * FF_),
        g_gh + ((size_t)(2 * bb + 1) * L_ + m0) * (2 * FF_)
    };
    const __nv_bfloat16* Bb[2] = {
        g_w2t + ((size_t)e0 * DM_ + n0) * (2 * FF_),
        g_w2t + ((size_t)e1 * DM_ + n0) * (2 * FF_)
    };

    uint32_t s0 = smem_u32(smem);
    const int wm = (wid >> 2) * 64, wn = (wid & 3) * 32;   // warp tile 64x32

    float acc[4][4][4] = {};
    const int NC = 64;   // 2 slots * (2048/64)

#define G2_LOAD(c, buf) do { \
        int _sl = (c) >> 5; int _k = ((c) & 31) * 64; uint32_t _d = s0 + (buf) * G2_STAGE; \
        load_tile<128>(_d,          Ab[_sl] + _k,       2 * FF_, tid); \
        load_tile<128>(_d + G2_A_L, Ab[_sl] + FF_ + _k, 2 * FF_, tid); \
        load_tile<128>(_d + G2_B_H, Bb[_sl] + _k,       2 * FF_, tid); \
        load_tile<128>(_d + G2_B_L, Bb[_sl] + FF_ + _k, 2 * FF_, tid); \
        CP_COMMIT(); } while (0)

    G2_LOAD(0, 0);
    G2_LOAD(1, 1);
    for (int c = 0; c < NC; c++) {
        if (c == NC - 1) asm volatile("cp.async.wait_group 0;" ::: "memory");
        else             asm volatile("cp.async.wait_group 1;" ::: "memory");
        __syncthreads();
        uint32_t sb = s0 + (uint32_t)(c & 1) * G2_STAGE;
        compute_pass<4, 4>(acc, sb,          sb + G2_B_H, wm, wn, lane);  // Ah*Bh
        compute_pass<4, 4>(acc, sb + G2_A_L, sb + G2_B_H, wm, wn, lane);  // Al*Bh
        compute_pass<4, 4>(acc, sb,          sb + G2_B_L, wm, wn, lane);  // Ah*Bl
        __syncthreads();
        if (c + 2 < NC) G2_LOAD(c + 2, (c + 2) & 1);
    }
#undef G2_LOAD

    const float* b2e0 = b2p + (size_t)e0 * DM_;
    const float* b2e1 = b2p + (size_t)e1 * DM_;
#pragma unroll
    for (int mf = 0; mf < 4; mf++) {
#pragma unroll
        for (int h = 0; h < 2; h++) {
            int r = m0 + wm + mf * 16 + (lane >> 2) + 8 * h;
            float* op = out + ((size_t)bb * L_ + r) * DM_;
#pragma unroll
            for (int nf = 0; nf < 4; nf++) {
                int n = n0 + wn + nf * 8 + (lane & 3) * 2;
                float2 v;
                v.x = acc[mf][nf][2 * h + 0] + g0 * __ldg(b2e0 + n)     + g1 * __ldg(b2e1 + n);
                v.y = acc[mf][nf][2 * h + 1] + g0 * __ldg(b2e0 + n + 1) + g1 * __ldg(b2e1 + n + 1);
                *(float2*)(op + n) = v;
            }
        }
    }
}

// ---------------------------------------------------------------------------
// launch — kernel launches + idempotent attribute opt-ins (no statics)
// ---------------------------------------------------------------------------
extern "C" void kernel_launch(void* const* d_in, const int* in_sizes, int n_in,
                              void* d_out, int out_size) {
    const float* x      = (const float*)d_in[0];
    const float* logits = (const float*)d_in[1];
    const int*   masks  = (const int*)  d_in[2];
    const float* W1     = (const float*)d_in[3];
    const float* b1     = (const float*)d_in[4];
    const float* W2     = (const float*)d_in[5];
    const float* b2     = (const float*)d_in[6];
    float* out = (float*)d_out;

    cudaFuncSetAttribute(gemm1_mma, cudaFuncAttributeMaxDynamicSharedMemorySize, G1_SMEM);
    cudaFuncSetAttribute(gemm2_mma, cudaFuncAttributeMaxDynamicSharedMemorySize, G2_SMEM);

    gates_kernel<<<1, 32>>>(logits, masks);

    size_t nx = (size_t)B_ * L_ * DM_;
    cvt_split_kernel<<<(unsigned)((nx + 255) / 256), 256>>>(x);

    dim3 tb(32, 8);
    transpose_cvt_w1<<<dim3(FF_ / 32, DM_ / 32, E_), tb>>>(W1);
    transpose_cvt_w2<<<dim3(DM_ / 32, FF_ / 32, E_), tb>>>(W2);

    gemm1_mma<<<dim3(FF_ / 256, L_ / 128, NPAIR), 256, G1_SMEM>>>(b1);
    gemm2_mma<<<dim3(DM_ / 128, L_ / 128, B_), 256, G2_SMEM>>>(b2, out);
}

// round 7
// speedup vs baseline: 4.4010x; 1.0520x over previous
#include <cuda_runtime.h>
#include <cuda_bf16.h>
#include <math.h>
#include <stdint.h>

#define B_   32
#define L_   256
#define DM_  512
#define FF_  2048
#define E_   8
#define NPAIR 64

// ---------------- device scratch (static = allocation-free) ----------------
__device__ int   g_pair_e[NPAIR];
__device__ float g_pair_g[NPAIR];
// x split:  [B*L][2*DM]   row = [hi(0..511) | lo(0..511)]
__device__ __align__(256) __nv_bfloat16 g_x2[(size_t)B_ * L_ * 2 * DM_];
// W1^T split: [E][FF][2*DM]
__device__ __align__(256) __nv_bfloat16 g_w1t[(size_t)E_ * FF_ * 2 * DM_];
// W2^T split: [E][DM][2*FF]
__device__ __align__(256) __nv_bfloat16 g_w2t[(size_t)E_ * DM_ * 2 * FF_];
// g*gelu(h) split: [pair][L][2*FF]
__device__ __align__(256) __nv_bfloat16 g_gh[(size_t)NPAIR * L_ * 2 * FF_];

// ---------------- helpers ----------------
__device__ __forceinline__ uint32_t smem_u32(const void* p) {
    uint32_t a;
    asm("{ .reg .u64 t; cvta.to.shared.u64 t, %1; cvt.u32.u64 %0, t; }" : "=r"(a) : "l"(p));
    return a;
}
__device__ __forceinline__ void cp16(uint32_t dst, const void* src) {
    asm volatile("cp.async.cg.shared.global [%0], [%1], 16;" :: "r"(dst), "l"(src));
}
#define CP_COMMIT() asm volatile("cp.async.commit_group;" ::: "memory")

__device__ __forceinline__ void ldsm_x4(uint32_t& r0, uint32_t& r1, uint32_t& r2, uint32_t& r3, uint32_t a) {
    asm volatile("ldmatrix.sync.aligned.m8n8.x4.shared.b16 {%0,%1,%2,%3}, [%4];"
                 : "=r"(r0), "=r"(r1), "=r"(r2), "=r"(r3) : "r"(a));
}
__device__ __forceinline__ void mma_bf16(float* c, const uint32_t* a, uint32_t b0, uint32_t b1) {
    asm volatile("mma.sync.aligned.m16n8k16.row.col.f32.bf16.bf16.f32 "
                 "{%0,%1,%2,%3}, {%4,%5,%6,%7}, {%8,%9}, {%0,%1,%2,%3};"
                 : "+f"(c[0]), "+f"(c[1]), "+f"(c[2]), "+f"(c[3])
                 : "r"(a[0]), "r"(a[1]), "r"(a[2]), "r"(a[3]), "r"(b0), "r"(b1));
}
__device__ __forceinline__ float gelu_exact(float x) {
    return 0.5f * x * (1.0f + erff(x * 0.70710678118654752440f));
}

// Load a ROWS x 64 bf16 tile (128B rows, XOR swizzle chunk^=(row&7)) via cp.async.
template<int ROWS, int NT>
__device__ __forceinline__ void load_tile(uint32_t dst, const __nv_bfloat16* src, int ld, int tid) {
    constexpr int ITER = ROWS * 8 / NT;
#pragma unroll
    for (int j = 0; j < ITER; j++) {
        int idx = tid + j * NT;
        int r = idx >> 3, c = idx & 7;
        uint32_t off = (uint32_t)(r * 128 + ((c ^ (r & 7)) * 16));
        cp16(dst + off, (const char*)src + (size_t)r * ld * 2 + c * 16);
    }
}

// Fused 3-term chunk: load Ah/Al/Bh/Bl fragments once, issue AhBh+AlBh+AhBl.
// Warp tile (MF*16) x (NF*8); all four operand tiles are kc=64-wide SMEM tiles.
template<int MF, int NF>
__device__ __forceinline__ void compute_fused(float (&acc)[MF][NF][4],
                                              uint32_t aH, uint32_t aL,
                                              uint32_t bH, uint32_t bL,
                                              int wm, int wn, int lane) {
#pragma unroll
    for (int ks = 0; ks < 4; ks++) {
        uint32_t ah[MF][4], al[MF][4];
#pragma unroll
        for (int mf = 0; mf < MF; mf++) {
            int r = wm + mf * 16 + (lane & 15);
            int c = ks * 2 + (lane >> 4);
            uint32_t off = (uint32_t)(r * 128 + ((c ^ (r & 7)) * 16));
            ldsm_x4(ah[mf][0], ah[mf][1], ah[mf][2], ah[mf][3], aH + off);
            ldsm_x4(al[mf][0], al[mf][1], al[mf][2], al[mf][3], aL + off);
        }
#pragma unroll
        for (int nfp = 0; nfp < NF / 2; nfp++) {
            // x4 covers both nf of the pair and both k-halves:
            // quad q: matrix = (nf + (q>>1), k-half q&1)
            int q = lane >> 3;
            int r = wn + (nfp * 2 + (q >> 1)) * 8 + (lane & 7);
            int c = ks * 2 + (q & 1);
            uint32_t off = (uint32_t)(r * 128 + ((c ^ (r & 7)) * 16));
            uint32_t bh0, bh1, bh2, bh3, bl0, bl1, bl2, bl3;
            ldsm_x4(bh0, bh1, bh2, bh3, bH + off);
            ldsm_x4(bl0, bl1, bl2, bl3, bL + off);
#pragma unroll
            for (int mf = 0; mf < MF; mf++) {
                mma_bf16(acc[mf][2 * nfp],     ah[mf], bh0, bh1);
                mma_bf16(acc[mf][2 * nfp + 1], ah[mf], bh2, bh3);
                mma_bf16(acc[mf][2 * nfp],     al[mf], bh0, bh1);
                mma_bf16(acc[mf][2 * nfp + 1], al[mf], bh2, bh3);
                mma_bf16(acc[mf][2 * nfp],     ah[mf], bl0, bl1);
                mma_bf16(acc[mf][2 * nfp + 1], ah[mf], bl2, bl3);
            }
        }
    }
}

// ---------------------------------------------------------------------------
// gates
// ---------------------------------------------------------------------------
__global__ void gates_kernel(const float* __restrict__ logits, const int* __restrict__ masks) {
    int b = threadIdx.x;
    if (b >= B_) return;
    float p[E_];
    float mx = -1e30f;
#pragma unroll
    for (int i = 0; i < E_; i++) { p[i] = logits[b * E_ + i]; mx = fmaxf(mx, p[i]); }
    float s = 0.0f;
#pragma unroll
    for (int i = 0; i < E_; i++) { p[i] = expf(p[i] - mx); s += p[i]; }
    float inv = 1.0f / s;
#pragma unroll
    for (int i = 0; i < E_; i++) p[i] = (masks[b * E_ + i] == 1) ? p[i] * inv : 0.0f;
    int i1 = 0;
#pragma unroll
    for (int i = 1; i < E_; i++) if (p[i] > p[i1]) i1 = i;
    int i2 = -1;
#pragma unroll
    for (int i = 0; i < E_; i++) {
        if (i == i1) continue;
        if (i2 < 0 || p[i] > p[i2]) i2 = i;
    }
    float denom = p[i1] + p[i2] + 1e-9f;
    g_pair_e[2 * b + 0] = i1;  g_pair_g[2 * b + 0] = p[i1] / denom;
    g_pair_e[2 * b + 1] = i2;  g_pair_g[2 * b + 1] = p[i2] / denom;
}

// ---------------------------------------------------------------------------
// prep kernels (device-symbol writes from device code only)
// ---------------------------------------------------------------------------
__global__ void cvt_split_kernel(const float* __restrict__ X) {
    size_t i = (size_t)blockIdx.x * blockDim.x + threadIdx.x;
    if (i >= (size_t)B_ * L_ * DM_) return;
    size_t row = i / DM_;
    int k = (int)(i % DM_);
    float v = X[i];
    __nv_bfloat16 h = __float2bfloat16(v);
    g_x2[row * (2 * DM_) + k] = h;
    g_x2[row * (2 * DM_) + DM_ + k] = __float2bfloat16(v - __bfloat162float(h));
}

template<int K, int N>
__device__ __forceinline__ void transpose_cvt_body(const float* __restrict__ W,
                                                   __nv_bfloat16* __restrict__ T) {
    __shared__ float s[32][33];
    int e = blockIdx.z;
    int n0 = blockIdx.x * 32, k0 = blockIdx.y * 32;
    const float* Wp = W + (size_t)e * K * N;
#pragma unroll
    for (int i = 0; i < 32; i += 8)
        s[threadIdx.y + i][threadIdx.x] = Wp[(size_t)(k0 + threadIdx.y + i) * N + n0 + threadIdx.x];
    __syncthreads();
#pragma unroll
    for (int i = 0; i < 32; i += 8) {
        int n = n0 + threadIdx.y + i;
        int k = k0 + threadIdx.x;
        float v = s[threadIdx.x][threadIdx.y + i];
        __nv_bfloat16 h = __float2bfloat16(v);
        __nv_bfloat16* rowp = T + ((size_t)e * N + n) * (2 * (size_t)K);
        rowp[k]     = h;
        rowp[K + k] = __float2bfloat16(v - __bfloat162float(h));
    }
}
__global__ void transpose_cvt_w1(const float* __restrict__ W) {
    transpose_cvt_body<DM_, FF_>(W, g_w1t);
}
__global__ void transpose_cvt_w2(const float* __restrict__ W) {
    transpose_cvt_body<FF_, DM_>(W, g_w2t);
}

// ---------------------------------------------------------------------------
// GEMM1: gh[pair] = g * gelu(x[b] @ W1[e] + b1[e]) -> bf16 hi/lo rows of 4096
// BM=128, BN=256, kc=64; stage = Ah16+Al16+Bh32+Bl32 = 96KB; 2 stages (192KB)
// 512 threads, 16 warps 4x4, warp tile 32x64 (MF=2, NF=8). Grid (8,2,64).
// ---------------------------------------------------------------------------
#define G1_STAGE  98304u
#define G1_A_L    16384u
#define G1_B_H    32768u
#define G1_B_L    65536u
#define G1_SMEM   (2 * 98304)

__global__ void __launch_bounds__(512, 1)
gemm1_mma(const float* __restrict__ b1p) {
    extern __shared__ __align__(128) char smem[];
    const int tid = threadIdx.x, lane = tid & 31, wid = tid >> 5;
    const int pair = blockIdx.z;
    const int e = g_pair_e[pair];
    const float g = g_pair_g[pair];
    const int m0 = blockIdx.y * 128, n0 = blockIdx.x * 256;

    const __nv_bfloat16* Abase = g_x2  + ((size_t)(pair >> 1) * L_ + m0) * (2 * DM_);
    const __nv_bfloat16* Bbase = g_w1t + ((size_t)e * FF_ + n0) * (2 * DM_);

    uint32_t s0 = smem_u32(smem);
    const int wm = (wid >> 2) * 32, wn = (wid & 3) * 64;   // warp tile 32x64

    float acc[2][8][4] = {};
    const int NC = 8;   // 512 / 64

#define G1_LOAD(c, buf) do { int _k = (c) * 64; uint32_t _d = s0 + (buf) * G1_STAGE; \
        load_tile<128, 512>(_d,          Abase + _k,       2 * DM_, tid); \
        load_tile<128, 512>(_d + G1_A_L, Abase + DM_ + _k, 2 * DM_, tid); \
        load_tile<256, 512>(_d + G1_B_H, Bbase + _k,       2 * DM_, tid); \
        load_tile<256, 512>(_d + G1_B_L, Bbase + DM_ + _k, 2 * DM_, tid); \
        CP_COMMIT(); } while (0)

    G1_LOAD(0, 0);
    G1_LOAD(1, 1);
    for (int c = 0; c < NC; c++) {
        if (c == NC - 1) asm volatile("cp.async.wait_group 0;" ::: "memory");
        else             asm volatile("cp.async.wait_group 1;" ::: "memory");
        __syncthreads();
        uint32_t sb = s0 + (uint32_t)(c & 1) * G1_STAGE;
        compute_fused<2, 8>(acc, sb, sb + G1_A_L, sb + G1_B_H, sb + G1_B_L, wm, wn, lane);
        __syncthreads();
        if (c + 2 < NC) G1_LOAD(c + 2, (c + 2) & 1);
    }
#undef G1_LOAD

    // epilogue: +bias, gelu, *gate, split hi/lo, store
    const float* b1e = b1p + (size_t)e * FF_;
#pragma unroll
    for (int mf = 0; mf < 2; mf++) {
#pragma unroll
        for (int h = 0; h < 2; h++) {
            int r = m0 + wm + mf * 16 + (lane >> 2) + 8 * h;
            __nv_bfloat16* rowp = g_gh + ((size_t)pair * L_ + r) * (2 * FF_);
#pragma unroll
            for (int nf = 0; nf < 8; nf++) {
                int n = n0 + wn + nf * 8 + (lane & 3) * 2;
                float v0 = acc[mf][nf][2 * h + 0] + __ldg(b1e + n);
                float v1 = acc[mf][nf][2 * h + 1] + __ldg(b1e + n + 1);
                v0 = gelu_exact(v0) * g;
                v1 = gelu_exact(v1) * g;
                __nv_bfloat16 h0 = __float2bfloat16(v0), h1 = __float2bfloat16(v1);
                __nv_bfloat162 hv; hv.x = h0; hv.y = h1;
                __nv_bfloat162 lv;
                lv.x = __float2bfloat16(v0 - __bfloat162float(h0));
                lv.y = __float2bfloat16(v1 - __bfloat162float(h1));
                *(__nv_bfloat162*)(rowp + n)       = hv;
                *(__nv_bfloat162*)(rowp + FF_ + n) = lv;
            }
        }
    }
}

// ---------------------------------------------------------------------------
// GEMM2: out[b] = sum_slot (g*h)[b,slot] @ W2[e_slot] + gated bias
// BM=128, BN=128, kc=64; stage = 64KB; 3 stages (192KB), 1 sync/iter.
// 512 threads, warp tile 32x32 (MF=2, NF=4). Grid (4,2,32) = 256 CTAs.
// ---------------------------------------------------------------------------
#define G2_STAGE  65536u
#define G2_A_L    16384u
#define G2_B_H    32768u
#define G2_B_L    49152u
#define G2_SMEM   (3 * 65536)

__global__ void __launch_bounds__(512, 1)
gemm2_mma(const float* __restrict__ b2p, float* __restrict__ out) {
    extern __shared__ __align__(128) char smem[];
    const int tid = threadIdx.x, lane = tid & 31, wid = tid >> 5;
    const int bb = blockIdx.z;
    const int m0 = blockIdx.y * 128, n0 = blockIdx.x * 128;
    const int e0 = g_pair_e[2 * bb + 0], e1 = g_pair_e[2 * bb + 1];
    const float g0 = g_pair_g[2 * bb + 0], g1 = g_pair_g[2 * bb + 1];

    const __nv_bfloat16* Ab[2] = {
        g_gh + ((size_t)(2 * bb + 0) * L_ + m0) * (2 * FF_),
        g_gh + ((size_t)(2 * bb + 1) * L_ + m0) * (2 * FF_)
    };
    const __nv_bfloat16* Bb[2] = {
        g_w2t + ((size_t)e0 * DM_ + n0) * (2 * FF_),
        g_w2t + ((size_t)e1 * DM_ + n0) * (2 * FF_)
    };

    uint32_t s0 = smem_u32(smem);
    const int wm = (wid >> 2) * 32, wn = (wid & 3) * 32;   // warp tile 32x32

    float acc[2][4][4] = {};
    const int NC = 64;   // 2 slots * (2048/64)

#define G2_LOAD(c, buf) do { \
        int _sl = (c) >> 5; int _k = ((c) & 31) * 64; uint32_t _d = s0 + (buf) * G2_STAGE; \
        load_tile<128, 512>(_d,          Ab[_sl] + _k,       2 * FF_, tid); \
        load_tile<128, 512>(_d + G2_A_L, Ab[_sl] + FF_ + _k, 2 * FF_, tid); \
        load_tile<128, 512>(_d + G2_B_H, Bb[_sl] + _k,       2 * FF_, tid); \
        load_tile<128, 512>(_d + G2_B_L, Bb[_sl] + FF_ + _k, 2 * FF_, tid); \
        CP_COMMIT(); } while (0)

    G2_LOAD(0, 0);
    G2_LOAD(1, 1);
    for (int c = 0; c < NC; c++) {
        if (c == NC - 1) asm volatile("cp.async.wait_group 0;" ::: "memory");
        else             asm volatile("cp.async.wait_group 1;" ::: "memory");
        __syncthreads();   // all warps done with buf (c+2)%3 (last read at c-1) + tile c visible
        if (c + 2 < NC) G2_LOAD(c + 2, (uint32_t)((c + 2) % 3));
        uint32_t sb = s0 + (uint32_t)(c % 3) * G2_STAGE;
        compute_fused<2, 4>(acc, sb, sb + G2_A_L, sb + G2_B_H, sb + G2_B_L, wm, wn, lane);
    }
#undef G2_LOAD

    const float* b2e0 = b2p + (size_t)e0 * DM_;
    const float* b2e1 = b2p + (size_t)e1 * DM_;
#pragma unroll
    for (int mf = 0; mf < 2; mf++) {
#pragma unroll
        for (int h = 0; h < 2; h++) {
            int r = m0 + wm + mf * 16 + (lane >> 2) + 8 * h;
            float* op = out + ((size_t)bb * L_ + r) * DM_;
#pragma unroll
            for (int nf = 0; nf < 4; nf++) {
                int n = n0 + wn + nf * 8 + (lane & 3) * 2;
                float2 v;
                v.x = acc[mf][nf][2 * h + 0] + g0 * __ldg(b2e0 + n)     + g1 * __ldg(b2e1 + n);
                v.y = acc[mf][nf][2 * h + 1] + g0 * __ldg(b2e0 + n + 1) + g1 * __ldg(b2e1 + n + 1);
                *(float2*)(op + n) = v;
            }
        }
    }
}

// ---------------------------------------------------------------------------
// launch — kernel launches + idempotent attribute opt-ins (no statics)
// ---------------------------------------------------------------------------
extern "C" void kernel_launch(void* const* d_in, const int* in_sizes, int n_in,
                              void* d_out, int out_size) {
    const float* x      = (const float*)d_in[0];
    const float* logits = (const float*)d_in[1];
    const int*   masks  = (const int*)  d_in[2];
    const float* W1     = (const float*)d_in[3];
    const float* b1     = (const float*)d_in[4];
    const float* W2     = (const float*)d_in[5];
    const float* b2     = (const float*)d_in[6];
    float* out = (float*)d_out;

    cudaFuncSetAttribute(gemm1_mma, cudaFuncAttributeMaxDynamicSharedMemorySize, G1_SMEM);
    cudaFuncSetAttribute(gemm2_mma, cudaFuncAttributeMaxDynamicSharedMemorySize, G2_SMEM);

    gates_kernel<<<1, 32>>>(logits, masks);

    size_t nx = (size_t)B_ * L_ * DM_;
    cvt_split_kernel<<<(unsigned)((nx + 255) / 256), 256>>>(x);

    dim3 tb(32, 8);
    transpose_cvt_w1<<<dim3(FF_ / 32, DM_ / 32, E_), tb>>>(W1);
    transpose_cvt_w2<<<dim3(DM_ / 32, FF_ / 32, E_), tb>>>(W2);

    gemm1_mma<<<dim3(FF_ / 256, L_ / 128, NPAIR), 512, G1_SMEM>>>(b1);
    gemm2_mma<<<dim3(DM_ / 128, L_ / 128, B_), 512, G2_SMEM>>>(b2, out);
}